// round 5
// baseline (speedup 1.0000x reference)
#include <cuda_runtime.h>

// Radon forward projection, sm_103a — round 5 (re-bench of R4; R4 bench was an
// infra failure, no signal). 768-thread blocks (4 angles x 192 dets) -> 24
// warps/SM at 1 CTA/SM, to feed the l1tex pipe (R3: L1=73%, issue=41%,
// smem-latency bound).

#define STRIDE_E 131
#define ROWS_E   131
#define SMEM_ELEMS (ROWS_E * STRIDE_E)        // 17161 entries (8 B each)
#define SMEM_BYTES (SMEM_ELEMS * 8 + 64)      // + trig table

#define N_ANG 285
#define N_DET 183
#define GRID_A 36                              // 36 blocks x 2 iters = 72 quads
#define NTHR   768

typedef unsigned long long u64;

__device__ __forceinline__ u64 pk2(float x, float y) {
    u64 u; asm("mov.b64 %0, {%1, %2};" : "=l"(u) : "f"(x), "f"(y)); return u;
}
__device__ __forceinline__ void upk2(u64 u, float& x, float& y) {
    asm("mov.b64 {%0, %1}, %2;" : "=f"(x), "=f"(y) : "l"(u));
}
__device__ __forceinline__ u64 fma2_(u64 a, u64 b, u64 c) {
    u64 d; asm("fma.rn.f32x2 %0, %1, %2, %3;" : "=l"(d) : "l"(a), "l"(b), "l"(c)); return d;
}
__device__ __forceinline__ u64 add2_(u64 a, u64 b) {
    u64 d; asm("add.rn.f32x2 %0, %1, %2;" : "=l"(d) : "l"(a), "l"(b)); return d;
}

__global__ __launch_bounds__(NTHR, 1)
void radon_fp_kernel(const float* __restrict__ x, float* __restrict__ out)
{
    extern __shared__ u64 imgs[];
    float2* trig = (float2*)(imgs + SMEM_ELEMS);

    const int tid = threadIdx.x;
    const int bp  = blockIdx.y;          // batch pair: batches 2bp, 2bp+1
    const int sub = tid / 192;           // which of 4 concurrent angles (0..3)
    const int det = tid % 192;

    const float* gx0 = x + (2 * bp)     * 16384;
    const float* gx1 = x + (2 * bp + 1) * 16384;

    // Fill padded dual-batch image: entry (ar, ac) = pixel (ar-1, ac-1), border 0.
    for (int e = tid; e < SMEM_ELEMS; e += NTHR) {
        int ar = e / STRIDE_E;
        int ac = e - ar * STRIDE_E;
        int pr = ar - 1, pc = ac - 1;
        bool in = ((unsigned)pr < 128u) & ((unsigned)pc < 128u);
        int gi = pr * 128 + pc;
        float v0 = in ? gx0[gi] : 0.0f;
        float v1 = in ? gx1[gi] : 0.0f;
        imgs[e] = pk2(v0, v1);
    }
    // Double-precision trig once per angle (8 angles per block), rest fp32.
    if (tid < 8) {
        int j = tid >> 2, sb = tid & 3;                 // iteration j, sub-angle sb
        int q = blockIdx.x + j * GRID_A;                // quad index
        int a = 4 * q + sb;
        if (q < 72 && a < N_ANG) {
            double sd, cd;
            sincospi((a + 0.5) / 285.0, &sd, &cd);
            trig[tid] = make_float2((float)sd, (float)cd);
        }
    }
    __syncthreads();

    // Constants (double-derived)
    const float RHOf = 28.284271247461902f;
    const float KD   = 0.47140452079103173f;        // DT/DX, DX = 0.3125
    const float t0c  = -28.284271247461902f + 0.5f * 0.14731391274719688f;
    const float scale = 0.012276159395599740f;      // DT/12
    const float s = fmaf((float)det + 0.5f, 2.0f * RHOf / 183.0f, -RHOf);

    const u64 BIG2   = pk2( 8388608.f,  8388608.f);
    const u64 nBIG2  = pk2(-8388608.f, -8388608.f);
    const u64 half2c = pk2(0.5f, 0.5f);
    const u64 neg1   = pk2(-1.f, -1.f);
    const u64 one2   = pk2(1.f, 1.f);
    const u64* imgm = imgs - 132;    // folds (x0+1)*131 + (x1+1) = flp0*131+flp1-132

    int j = 0;
    for (int q = blockIdx.x; q < 72; q += GRID_A, ++j) {
        int a = 4 * q + sub;
        if (det < N_DET && a < N_ANG) {
            float2 sc = trig[j * 4 + sub];
            float sn = sc.x, cs = sc.y;
            float d0 = KD * cs;
            float d1 = KD * sn;
            // i0 = (-s*sn + t*cs + 20)*3.2 - 0.5, t = t0c + k*DT
            float c0 = fmaf(-s, sn, fmaf(t0c, cs, 20.0f)) * 3.2f - 0.5f;
            float c1 = fmaf( s, cs, fmaf(t0c, sn, 20.0f)) * 3.2f - 0.5f;

            // Valid window (content zero outside i in (-1, 128); safe to 129.49)
            const float LO = -0.999f, HI = 128.01f;
            float ra = (LO - c0) / d0, rb = (HI - c0) / d0;
            float klo = fmaxf(0.0f,  fminf(ra, rb));
            float khi = fminf(383.0f, fmaxf(ra, rb));
            ra = (LO - c1) / d1; rb = (HI - c1) / d1;
            klo = fmaxf(klo, fminf(ra, rb));
            khi = fminf(khi, fmaxf(ra, rb));
            int k0 = (int)ceilf(klo);
            int k1 = (int)floorf(khi);

            u64 d01  = pk2(d0, d1);
            u64 c01m = pk2(c0 + 1.5f, c1 + 1.5f);   // t = i + 1.5
            u64 kf2  = pk2((float)k0, (float)k0);
            u64 acc2 = 0ull;

            #pragma unroll 4
            for (int k = k0; k <= k1; ++k) {
                u64 t01  = fma2_(kf2, d01, c01m);        // i+1.5, both axes
                u64 y01  = add2_(t01, BIG2);             // round-to-int in mantissa
                u64 fl01 = add2_(y01, nBIG2);            // round(t) = floor(i)+2
                u64 fr01 = add2_(fma2_(fl01, neg1, t01), half2c); // frac in [0,1]
                kf2 = add2_(kf2, one2);
                float yl, yh; upk2(y01, yl, yh);
                int n0 = __float_as_int(yl) & 255;       // floor(i0)+2 in [1,130]
                int n1 = __float_as_int(yh) & 255;
                int idx = n0 * STRIDE_E + n1;
                u64 p00 = imgm[idx];
                u64 p01 = imgm[idx + 1];
                u64 p10 = imgm[idx + STRIDE_E];
                u64 p11 = imgm[idx + STRIDE_E + 1];
                float f0, f1; upk2(fr01, f0, f1);
                u64 f0_2 = pk2(f0, f0);
                u64 f1_2 = pk2(f1, f1);
                u64 m0  = fma2_(f1_2, fma2_(p00, neg1, p01), p00);
                u64 m1  = fma2_(f1_2, fma2_(p10, neg1, p11), p10);
                u64 res = fma2_(f0_2, fma2_(m0, neg1, m1), m0);
                acc2 = add2_(acc2, res);
            }

            float o0, o1; upk2(acc2, o0, o1);
            int ob = ((2 * bp) * N_ANG + a) * N_DET + det;
            out[ob] = o0 * scale;
            out[ob + N_ANG * N_DET] = o1 * scale;
        }
    }
}

extern "C" void kernel_launch(void* const* d_in, const int* in_sizes, int n_in,
                              void* d_out, int out_size)
{
    const float* x = (const float*)d_in[0];
    float* out = (float*)d_out;

    static bool attr_set = false;
    if (!attr_set) {
        cudaFuncSetAttribute(radon_fp_kernel,
                             cudaFuncAttributeMaxDynamicSharedMemorySize, SMEM_BYTES);
        attr_set = true;
    }

    dim3 grid(GRID_A, 4);
    radon_fp_kernel<<<grid, NTHR, SMEM_BYTES>>>(x, out);
}

// round 6
// speedup vs baseline: 1.1962x; 1.1962x over previous
#include <cuda_runtime.h>
#include <cuda_fp16.h>

// Radon forward projection, sm_103a — round 6.
// R5 showed the smem crossbar (with ~1.64x bank conflicts) is the binding pipe
// (L1 pinned at 74% across occ 15%->31%). This round halves crossbar work per
// sample: 4 batches packed as fp16x4 per 8-byte smem entry; taps converted to
// fp32 in-register; bilinear + accumulation stay fp32 (tap-quantization error
// ~2.8e-4 rms, under the 1e-3 gate).

#define STRIDE_E 131
#define ROWS_E   131
#define SMEM_ELEMS (ROWS_E * STRIDE_E)        // 17161 entries (8 B each)
#define SMEM_BYTES (SMEM_ELEMS * 8 + 64)      // + trig table

#define N_ANG 285
#define N_DET 183
#define SINO  (N_ANG * N_DET)                 // 52155
#define NTHR  768

typedef unsigned long long u64;

__device__ __forceinline__ u64 pk2(float x, float y) {
    u64 u; asm("mov.b64 %0, {%1, %2};" : "=l"(u) : "f"(x), "f"(y)); return u;
}
__device__ __forceinline__ void upk2(u64 u, float& x, float& y) {
    asm("mov.b64 {%0, %1}, %2;" : "=f"(x), "=f"(y) : "l"(u));
}
__device__ __forceinline__ u64 fma2_(u64 a, u64 b, u64 c) {
    u64 d; asm("fma.rn.f32x2 %0, %1, %2, %3;" : "=l"(d) : "l"(a), "l"(b), "l"(c)); return d;
}
__device__ __forceinline__ u64 add2_(u64 a, u64 b) {
    u64 d; asm("add.rn.f32x2 %0, %1, %2;" : "=l"(d) : "l"(a), "l"(b)); return d;
}
// Unpack fp16x4 (u64) -> two f32x2: A = {f32(h0), f32(h1)}, B = {f32(h2), f32(h3)}
__device__ __forceinline__ void h4f4(u64 q, u64& A, u64& B) {
    asm("{\n\t"
        ".reg .b16 h0,h1,h2,h3;\n\t"
        ".reg .f32 g0,g1,g2,g3;\n\t"
        "mov.b64 {h0,h1,h2,h3}, %2;\n\t"
        "cvt.f32.f16 g0, h0;\n\t"
        "cvt.f32.f16 g1, h1;\n\t"
        "cvt.f32.f16 g2, h2;\n\t"
        "cvt.f32.f16 g3, h3;\n\t"
        "mov.b64 %0, {g0,g1};\n\t"
        "mov.b64 %1, {g2,g3};\n\t"
        "}" : "=l"(A), "=l"(B) : "l"(q));
}

__global__ __launch_bounds__(NTHR, 1)
void radon_fp_kernel(const float* __restrict__ x, float* __restrict__ out)
{
    extern __shared__ u64 imgs[];
    float2* trig = (float2*)(imgs + SMEM_ELEMS);

    const int tid = threadIdx.x;
    const int bg  = blockIdx.y;          // batch group: batches 4bg .. 4bg+3
    const int sub = tid / 192;           // which of 4 concurrent angles (0..3)
    const int det = tid % 192;

    const float* gx0 = x + (4 * bg)     * 16384;
    const float* gx1 = x + (4 * bg + 1) * 16384;
    const float* gx2 = x + (4 * bg + 2) * 16384;
    const float* gx3 = x + (4 * bg + 3) * 16384;

    // Fill padded 4-batch fp16 image: entry (ar, ac) = pixel (ar-1, ac-1), border 0.
    for (int e = tid; e < SMEM_ELEMS; e += NTHR) {
        int ar = e / STRIDE_E;
        int ac = e - ar * STRIDE_E;
        int pr = ar - 1, pc = ac - 1;
        bool in = ((unsigned)pr < 128u) & ((unsigned)pc < 128u);
        int gi = pr * 128 + pc;
        float v0 = in ? gx0[gi] : 0.0f;
        float v1 = in ? gx1[gi] : 0.0f;
        float v2 = in ? gx2[gi] : 0.0f;
        float v3 = in ? gx3[gi] : 0.0f;
        __half2 L = __floats2half2_rn(v0, v1);   // x=v0 (low bits)
        __half2 H = __floats2half2_rn(v2, v3);
        unsigned lo = reinterpret_cast<unsigned&>(L);
        unsigned hi = reinterpret_cast<unsigned&>(H);
        imgs[e] = ((u64)hi << 32) | (u64)lo;
    }
    // Double-precision trig for this block's 4 angles.
    if (tid < 4) {
        int a = 4 * blockIdx.x + tid;
        if (a < N_ANG) {
            double sd, cd;
            sincospi((a + 0.5) / 285.0, &sd, &cd);
            trig[tid] = make_float2((float)sd, (float)cd);
        }
    }
    __syncthreads();

    // Constants (double-derived)
    const float RHOf = 28.284271247461902f;
    const float KD   = 0.47140452079103173f;        // DT/DX, DX = 0.3125
    const float t0c  = -28.284271247461902f + 0.5f * 0.14731391274719688f;
    const float scale = 0.012276159395599740f;      // DT/12
    const float s = fmaf((float)det + 0.5f, 2.0f * RHOf / 183.0f, -RHOf);

    const u64 BIG2   = pk2( 8388608.f,  8388608.f);
    const u64 nBIG2  = pk2(-8388608.f, -8388608.f);
    const u64 half2c = pk2(0.5f, 0.5f);
    const u64 neg1   = pk2(-1.f, -1.f);
    const u64 one2   = pk2(1.f, 1.f);
    const u64* imgm = imgs - 132;    // folds (x0+1)*131 + (x1+1) = flp0*131+flp1-132

    const int a = 4 * blockIdx.x + sub;
    if (det < N_DET && a < N_ANG) {
        float2 sc = trig[sub];
        float sn = sc.x, cs = sc.y;
        float d0 = KD * cs;
        float d1 = KD * sn;
        // i0 = (-s*sn + t*cs + 20)*3.2 - 0.5, t = t0c + k*DT
        float c0 = fmaf(-s, sn, fmaf(t0c, cs, 20.0f)) * 3.2f - 0.5f;
        float c1 = fmaf( s, cs, fmaf(t0c, sn, 20.0f)) * 3.2f - 0.5f;

        // Valid window (content zero outside i in (-1, 128); safe to 129.49)
        const float LO = -0.999f, HI = 128.01f;
        float ra = (LO - c0) / d0, rb = (HI - c0) / d0;
        float klo = fmaxf(0.0f,  fminf(ra, rb));
        float khi = fminf(383.0f, fmaxf(ra, rb));
        ra = (LO - c1) / d1; rb = (HI - c1) / d1;
        klo = fmaxf(klo, fminf(ra, rb));
        khi = fminf(khi, fmaxf(ra, rb));
        int k0 = (int)ceilf(klo);
        int k1 = (int)floorf(khi);

        u64 d01  = pk2(d0, d1);
        u64 c01m = pk2(c0 + 1.5f, c1 + 1.5f);   // t = i + 1.5
        u64 kf2  = pk2((float)k0, (float)k0);
        u64 accA = 0ull;                        // batches 0,1
        u64 accB = 0ull;                        // batches 2,3

        #pragma unroll 2
        for (int k = k0; k <= k1; ++k) {
            u64 t01  = fma2_(kf2, d01, c01m);        // i+1.5, both axes
            u64 y01  = add2_(t01, BIG2);             // round-to-int in mantissa
            u64 fl01 = add2_(y01, nBIG2);            // round(t) = floor(i)+2
            u64 fr01 = add2_(fma2_(fl01, neg1, t01), half2c); // frac in [0,1]
            kf2 = add2_(kf2, one2);
            float yl, yh; upk2(y01, yl, yh);
            int n0 = __float_as_int(yl) & 255;       // floor(i0)+2 in [1,130]
            int n1 = __float_as_int(yh) & 255;
            int idx = n0 * STRIDE_E + n1;
            u64 q00 = imgm[idx];
            u64 q01 = imgm[idx + 1];
            u64 q10 = imgm[idx + STRIDE_E];
            u64 q11 = imgm[idx + STRIDE_E + 1];
            float f0, f1; upk2(fr01, f0, f1);
            u64 f0_2 = pk2(f0, f0);
            u64 f1_2 = pk2(f1, f1);
            u64 a00, b00, a01, b01, a10, b10, a11, b11;
            h4f4(q00, a00, b00);
            h4f4(q01, a01, b01);
            h4f4(q10, a10, b10);
            h4f4(q11, a11, b11);
            // batches 0,1
            u64 mA0 = fma2_(f1_2, fma2_(a00, neg1, a01), a00);
            u64 mA1 = fma2_(f1_2, fma2_(a10, neg1, a11), a10);
            accA = add2_(accA, fma2_(f0_2, fma2_(mA0, neg1, mA1), mA0));
            // batches 2,3
            u64 mB0 = fma2_(f1_2, fma2_(b00, neg1, b01), b00);
            u64 mB1 = fma2_(f1_2, fma2_(b10, neg1, b11), b10);
            accB = add2_(accB, fma2_(f0_2, fma2_(mB0, neg1, mB1), mB0));
        }

        int ob = ((4 * bg) * N_ANG + a) * N_DET + det;
        float o0, o1, o2, o3;
        upk2(accA, o0, o1);
        upk2(accB, o2, o3);
        out[ob]            = o0 * scale;
        out[ob + SINO]     = o1 * scale;
        out[ob + 2 * SINO] = o2 * scale;
        out[ob + 3 * SINO] = o3 * scale;
    }
}

extern "C" void kernel_launch(void* const* d_in, const int* in_sizes, int n_in,
                              void* d_out, int out_size)
{
    const float* x = (const float*)d_in[0];
    float* out = (float*)d_out;

    static bool attr_set = false;
    if (!attr_set) {
        cudaFuncSetAttribute(radon_fp_kernel,
                             cudaFuncAttributeMaxDynamicSharedMemorySize, SMEM_BYTES);
        attr_set = true;
    }

    dim3 grid(72, 2);    // 72 angle-quads x 2 batch-groups = 144 blocks (1 wave)
    radon_fp_kernel<<<grid, NTHR, SMEM_BYTES>>>(x, out);
}

// round 7
// speedup vs baseline: 1.5991x; 1.3368x over previous
#include <cuda_runtime.h>
#include <cuda_fp16.h>

// Radon forward projection, sm_103a — round 7.
// R6 left the kernel issue/latency bound (issue 54%, fma 50%, L1 45%), with 16
// cvt.f32.f16 per iteration dominating the math stream. This round blends in
// fp16 (HSUB2/HFMA2) and converts only the blended result (16 cvts -> 6), and
// unrolls 4x for LDS latency hiding. Accumulation stays fp32.

#define STRIDE_E 131
#define ROWS_E   131
#define SMEM_ELEMS (ROWS_E * STRIDE_E)        // 17161 entries (8 B each)
#define SMEM_BYTES (SMEM_ELEMS * 8 + 64)      // + trig table

#define N_ANG 285
#define N_DET 183
#define SINO  (N_ANG * N_DET)                 // 52155
#define NTHR  768

typedef unsigned long long u64;

__device__ __forceinline__ u64 pk2(float x, float y) {
    u64 u; asm("mov.b64 %0, {%1, %2};" : "=l"(u) : "f"(x), "f"(y)); return u;
}
__device__ __forceinline__ void upk2(u64 u, float& x, float& y) {
    asm("mov.b64 {%0, %1}, %2;" : "=f"(x), "=f"(y) : "l"(u));
}
__device__ __forceinline__ u64 fma2_(u64 a, u64 b, u64 c) {
    u64 d; asm("fma.rn.f32x2 %0, %1, %2, %3;" : "=l"(d) : "l"(a), "l"(b), "l"(c)); return d;
}
__device__ __forceinline__ u64 add2_(u64 a, u64 b) {
    u64 d; asm("add.rn.f32x2 %0, %1, %2;" : "=l"(d) : "l"(a), "l"(b)); return d;
}
__device__ __forceinline__ __half2 as_h2(unsigned u) {
    __half2 h; asm("mov.b32 %0, %1;" : "=r"(reinterpret_cast<unsigned&>(h)) : "r"(u)); return h;
}

__global__ __launch_bounds__(NTHR, 1)
void radon_fp_kernel(const float* __restrict__ x, float* __restrict__ out)
{
    extern __shared__ u64 imgs[];
    float2* trig = (float2*)(imgs + SMEM_ELEMS);

    const int tid = threadIdx.x;
    const int bg  = blockIdx.y;          // batch group: batches 4bg .. 4bg+3
    const int sub = tid / 192;           // which of 4 concurrent angles (0..3)
    const int det = tid % 192;

    const float* gx0 = x + (4 * bg)     * 16384;
    const float* gx1 = x + (4 * bg + 1) * 16384;
    const float* gx2 = x + (4 * bg + 2) * 16384;
    const float* gx3 = x + (4 * bg + 3) * 16384;

    // Fill padded 4-batch fp16 image: entry (ar, ac) = pixel (ar-1, ac-1), border 0.
    for (int e = tid; e < SMEM_ELEMS; e += NTHR) {
        int ar = e / STRIDE_E;
        int ac = e - ar * STRIDE_E;
        int pr = ar - 1, pc = ac - 1;
        bool in = ((unsigned)pr < 128u) & ((unsigned)pc < 128u);
        int gi = pr * 128 + pc;
        float v0 = in ? gx0[gi] : 0.0f;
        float v1 = in ? gx1[gi] : 0.0f;
        float v2 = in ? gx2[gi] : 0.0f;
        float v3 = in ? gx3[gi] : 0.0f;
        __half2 L = __floats2half2_rn(v0, v1);
        __half2 H = __floats2half2_rn(v2, v3);
        unsigned lo = reinterpret_cast<unsigned&>(L);
        unsigned hi = reinterpret_cast<unsigned&>(H);
        imgs[e] = ((u64)hi << 32) | (u64)lo;
    }
    // Double-precision trig for this block's 4 angles.
    if (tid < 4) {
        int a = 4 * blockIdx.x + tid;
        if (a < N_ANG) {
            double sd, cd;
            sincospi((a + 0.5) / 285.0, &sd, &cd);
            trig[tid] = make_float2((float)sd, (float)cd);
        }
    }
    __syncthreads();

    // Constants (double-derived)
    const float RHOf = 28.284271247461902f;
    const float KD   = 0.47140452079103173f;        // DT/DX, DX = 0.3125
    const float t0c  = -28.284271247461902f + 0.5f * 0.14731391274719688f;
    const float scale = 0.012276159395599740f;      // DT/12
    const float s = fmaf((float)det + 0.5f, 2.0f * RHOf / 183.0f, -RHOf);

    const u64 BIG2   = pk2( 8388608.f,  8388608.f);
    const u64 nBIG2  = pk2(-8388608.f, -8388608.f);
    const u64 half2c = pk2(0.5f, 0.5f);
    const u64 neg1   = pk2(-1.f, -1.f);
    const u64 one2   = pk2(1.f, 1.f);
    const uint2* img2 = ((const uint2*)imgs) - 132;  // folds +STRIDE+1 base shift

    const int a = 4 * blockIdx.x + sub;
    if (det < N_DET && a < N_ANG) {
        float2 sc = trig[sub];
        float sn = sc.x, cs = sc.y;
        float d0 = KD * cs;
        float d1 = KD * sn;
        // i0 = (-s*sn + t*cs + 20)*3.2 - 0.5, t = t0c + k*DT
        float c0 = fmaf(-s, sn, fmaf(t0c, cs, 20.0f)) * 3.2f - 0.5f;
        float c1 = fmaf( s, cs, fmaf(t0c, sn, 20.0f)) * 3.2f - 0.5f;

        // Valid window (content zero outside i in (-1, 128); safe to 129.49)
        const float LO = -0.999f, HI = 128.01f;
        float ra = (LO - c0) / d0, rb = (HI - c0) / d0;
        float klo = fmaxf(0.0f,  fminf(ra, rb));
        float khi = fminf(383.0f, fmaxf(ra, rb));
        ra = (LO - c1) / d1; rb = (HI - c1) / d1;
        klo = fmaxf(klo, fminf(ra, rb));
        khi = fminf(khi, fmaxf(ra, rb));
        int k0 = (int)ceilf(klo);
        int k1 = (int)floorf(khi);

        u64 d01  = pk2(d0, d1);
        u64 c01m = pk2(c0 + 1.5f, c1 + 1.5f);   // t = i + 1.5
        u64 kf2  = pk2((float)k0, (float)k0);
        u64 accA = 0ull;                        // batches 0,1 (fp32 pair)
        u64 accB = 0ull;                        // batches 2,3

        #pragma unroll 4
        for (int k = k0; k <= k1; ++k) {
            u64 t01  = fma2_(kf2, d01, c01m);        // i+1.5, both axes
            u64 y01  = add2_(t01, BIG2);             // round-to-int in mantissa
            u64 fl01 = add2_(y01, nBIG2);            // round(t) = floor(i)+2
            u64 fr01 = add2_(fma2_(fl01, neg1, t01), half2c); // frac in [0,1]
            kf2 = add2_(kf2, one2);
            int n0 = (int)((unsigned)y01 & 255u);          // floor(i0)+2 in [1,130]
            int n1 = (int)((unsigned)(y01 >> 32) & 255u);  // floor(i1)+2
            int idx = n0 * STRIDE_E + n1;
            uint2 q00 = img2[idx];
            uint2 q01 = img2[idx + 1];
            uint2 q10 = img2[idx + STRIDE_E];
            uint2 q11 = img2[idx + STRIDE_E + 1];
            float f0, f1; upk2(fr01, f0, f1);
            __half2 f0h = __float2half2_rn(f0);
            __half2 f1h = __float2half2_rn(f1);
            // batches 0,1 (low words)
            {
                __half2 a00 = as_h2(q00.x), a01 = as_h2(q01.x);
                __half2 a10 = as_h2(q10.x), a11 = as_h2(q11.x);
                __half2 m0 = __hfma2(f1h, __hsub2(a01, a00), a00);
                __half2 m1 = __hfma2(f1h, __hsub2(a11, a10), a10);
                __half2 r  = __hfma2(f0h, __hsub2(m1, m0), m0);
                accA = add2_(accA, pk2(__low2float(r), __high2float(r)));
            }
            // batches 2,3 (high words)
            {
                __half2 b00 = as_h2(q00.y), b01 = as_h2(q01.y);
                __half2 b10 = as_h2(q10.y), b11 = as_h2(q11.y);
                __half2 m0 = __hfma2(f1h, __hsub2(b01, b00), b00);
                __half2 m1 = __hfma2(f1h, __hsub2(b11, b10), b10);
                __half2 r  = __hfma2(f0h, __hsub2(m1, m0), m0);
                accB = add2_(accB, pk2(__low2float(r), __high2float(r)));
            }
        }

        int ob = ((4 * bg) * N_ANG + a) * N_DET + det;
        float o0, o1, o2, o3;
        upk2(accA, o0, o1);
        upk2(accB, o2, o3);
        out[ob]            = o0 * scale;
        out[ob + SINO]     = o1 * scale;
        out[ob + 2 * SINO] = o2 * scale;
        out[ob + 3 * SINO] = o3 * scale;
    }
}

extern "C" void kernel_launch(void* const* d_in, const int* in_sizes, int n_in,
                              void* d_out, int out_size)
{
    const float* x = (const float*)d_in[0];
    float* out = (float*)d_out;

    static bool attr_set = false;
    if (!attr_set) {
        cudaFuncSetAttribute(radon_fp_kernel,
                             cudaFuncAttributeMaxDynamicSharedMemorySize, SMEM_BYTES);
        attr_set = true;
    }

    dim3 grid(72, 2);    // 72 angle-quads x 2 batch-groups = 144 blocks (1 wave)
    radon_fp_kernel<<<grid, NTHR, SMEM_BYTES>>>(x, out);
}